// round 1
// baseline (speedup 1.0000x reference)
#include <cuda_runtime.h>
#include <cstdint>

#define SEQ 2048
#define DIM 2048
#define NH  16
#define HD  128
#define TD  (3*DIM)
#define LN_EPS 1e-5f

// ---------------- scratch (static device globals; no allocation) ----------------
__device__ float g_xn[(size_t)SEQ*DIM];     // 16 MB  LayerNorm output (also residual)
__device__ float g_qkv[(size_t)SEQ*TD];     // 48 MB  QKV projection output
__device__ float g_attn[(size_t)SEQ*DIM];   // 16 MB  attention output [S, H*HD]

__device__ __forceinline__ float4 ld4(const float* p){ return *(const float4*)p; }

// ======================= kernel 1: fused embed + LayerNorm =======================
__global__ void __launch_bounds__(256) k_embed_ln(
    const float* __restrict__ byte_repr,
    const int*   __restrict__ cats,
    const int*   __restrict__ cse,
    const int*   __restrict__ comb,
    const float* __restrict__ cat_emb,
    const float* __restrict__ case_emb,
    const float* __restrict__ comb_emb,
    const float* __restrict__ g,
    const float* __restrict__ b)
{
    int s = blockIdx.x;
    int t = threadIdx.x;
    int lane = t & 31, wid = t >> 5;
    int c0 = t * 4;          // cols c0..c0+3
    int c1 = 1024 + t * 4;   // cols c1..c1+3

    size_t catb = (size_t)cats[s] * DIM;
    size_t cab  = (size_t)cse[s]  * DIM;
    size_t cob  = (size_t)comb[s] * DIM;
    const float* base = byte_repr + (size_t)s * DIM;

    float x[8];
    {
        float4 a = ld4(base + c0), e = ld4(cat_emb + catb + c0);
        float4 f = ld4(case_emb + cab + c0), h = ld4(comb_emb + cob + c0);
        x[0] = a.x + e.x + f.x + h.x;  x[1] = a.y + e.y + f.y + h.y;
        x[2] = a.z + e.z + f.z + h.z;  x[3] = a.w + e.w + f.w + h.w;
    }
    {
        float4 a = ld4(base + c1), e = ld4(cat_emb + catb + c1);
        float4 f = ld4(case_emb + cab + c1), h = ld4(comb_emb + cob + c1);
        x[4] = a.x + e.x + f.x + h.x;  x[5] = a.y + e.y + f.y + h.y;
        x[6] = a.z + e.z + f.z + h.z;  x[7] = a.w + e.w + f.w + h.w;
    }

    __shared__ float red[8];
    __shared__ float s_bcast;

    // mean
    float sum = 0.f;
    #pragma unroll
    for (int i = 0; i < 8; i++) sum += x[i];
    #pragma unroll
    for (int o = 16; o > 0; o >>= 1) sum += __shfl_xor_sync(0xffffffffu, sum, o);
    if (lane == 0) red[wid] = sum;
    __syncthreads();
    if (t == 0) {
        float v = 0.f;
        #pragma unroll
        for (int i = 0; i < 8; i++) v += red[i];
        s_bcast = v * (1.0f / DIM);
    }
    __syncthreads();
    float mu = s_bcast;
    __syncthreads();

    // variance
    float sq = 0.f;
    #pragma unroll
    for (int i = 0; i < 8; i++) { float d = x[i] - mu; sq += d * d; }
    #pragma unroll
    for (int o = 16; o > 0; o >>= 1) sq += __shfl_xor_sync(0xffffffffu, sq, o);
    if (lane == 0) red[wid] = sq;
    __syncthreads();
    if (t == 0) {
        float v = 0.f;
        #pragma unroll
        for (int i = 0; i < 8; i++) v += red[i];
        s_bcast = rsqrtf(v * (1.0f / DIM) + LN_EPS);
    }
    __syncthreads();
    float rs = s_bcast;

    float* dst = g_xn + (size_t)s * DIM;
    {
        float4 gg = ld4(g + c0), bb = ld4(b + c0);
        float4 o;
        o.x = (x[0] - mu) * rs * gg.x + bb.x;
        o.y = (x[1] - mu) * rs * gg.y + bb.y;
        o.z = (x[2] - mu) * rs * gg.z + bb.z;
        o.w = (x[3] - mu) * rs * gg.w + bb.w;
        *(float4*)(dst + c0) = o;
    }
    {
        float4 gg = ld4(g + c1), bb = ld4(b + c1);
        float4 o;
        o.x = (x[4] - mu) * rs * gg.x + bb.x;
        o.y = (x[5] - mu) * rs * gg.y + bb.y;
        o.z = (x[6] - mu) * rs * gg.z + bb.z;
        o.w = (x[7] - mu) * rs * gg.w + bb.w;
        *(float4*)(dst + c1) = o;
    }
}

// ================= kernel 2/4: SGEMM-NT  C[m,n] = sum_k A[m,k]*B[n,k] + bias[n] (+resid) =================
// BM=BN=128, BK=16, 256 threads, 8x8 microtile with strided (interleaved) mapping.
__global__ void __launch_bounds__(256) k_sgemm_nt(
    const float* __restrict__ A, const float* __restrict__ B,
    const float* __restrict__ bias, const float* __restrict__ resid,
    float* __restrict__ C, int M, int N, int K)
{
    __shared__ float As[16][129];
    __shared__ float Bs[16][129];

    int bm = blockIdx.y * 128;
    int bn = blockIdx.x * 128;
    int t = threadIdx.x;
    int tx = t & 15, ty = t >> 4;

    float acc[8][8];
    #pragma unroll
    for (int i = 0; i < 8; i++)
        #pragma unroll
        for (int j = 0; j < 8; j++) acc[i][j] = 0.f;

    for (int kt = 0; kt < K; kt += 16) {
        #pragma unroll
        for (int i = 0; i < 2; i++) {
            int vid = t + i * 256;
            int row = vid >> 2;
            int c4  = (vid & 3) * 4;
            float4 a = ld4(A + (size_t)(bm + row) * K + kt + c4);
            As[c4 + 0][row] = a.x; As[c4 + 1][row] = a.y;
            As[c4 + 2][row] = a.z; As[c4 + 3][row] = a.w;
            float4 bb = ld4(B + (size_t)(bn + row) * K + kt + c4);
            Bs[c4 + 0][row] = bb.x; Bs[c4 + 1][row] = bb.y;
            Bs[c4 + 2][row] = bb.z; Bs[c4 + 3][row] = bb.w;
        }
        __syncthreads();

        #pragma unroll
        for (int k = 0; k < 16; k++) {
            float af[8], bf[8];
            #pragma unroll
            for (int i = 0; i < 8; i++) af[i] = As[k][ty + 16 * i];
            #pragma unroll
            for (int j = 0; j < 8; j++) bf[j] = Bs[k][tx + 16 * j];
            #pragma unroll
            for (int i = 0; i < 8; i++)
                #pragma unroll
                for (int j = 0; j < 8; j++)
                    acc[i][j] += af[i] * bf[j];
        }
        __syncthreads();
    }

    #pragma unroll
    for (int i = 0; i < 8; i++) {
        int m = bm + ty + 16 * i;
        #pragma unroll
        for (int j = 0; j < 8; j++) {
            int n = bn + tx + 16 * j;
            float v = acc[i][j] + bias[n];
            if (resid) v += resid[(size_t)m * N + n];
            C[(size_t)m * N + n] = v;
        }
    }
}

// ======================= kernel 3: flash-style attention =======================
// grid (SEQ/64, NH), 256 threads (16x16). BQ=BK=64. Online softmax.
#define QK_STRIDE 132
#define P_STRIDE   68
#define ATTN_SMEM ((64*QK_STRIDE*2 + 64*P_STRIDE) * 4 + 128 * 4)

__global__ void __launch_bounds__(256) k_attn(const int* __restrict__ seg)
{
    extern __shared__ float sm[];
    float* qs = sm;                         // [64][132]
    float* ks = qs + 64 * QK_STRIDE;        // [64][132]  (K tile, then reused for V)
    float* ps = ks + 64 * QK_STRIDE;        // [64][68]
    int*   sq = (int*)(ps + 64 * P_STRIDE); // [64]
    int*   sk = sq + 64;                    // [64]

    int q0 = blockIdx.x * 64;
    int h  = blockIdx.y;
    int t = threadIdx.x;
    int tx = t & 15, ty = t >> 4;
    const float scale = 0.08838834764831845f; // 1/sqrt(128)

    // load Q tile (pre-scaled)
    #pragma unroll
    for (int i = 0; i < 8; i++) {
        int vid = t + i * 256;
        int row = vid >> 5;
        int c4  = (vid & 31) * 4;
        float4 v = ld4(g_qkv + (size_t)(q0 + row) * TD + h * HD + c4);
        float* d = qs + row * QK_STRIDE + c4;
        d[0] = v.x * scale; d[1] = v.y * scale; d[2] = v.z * scale; d[3] = v.w * scale;
    }
    if (t < 64) sq[t] = seg[q0 + t];

    float m_i[4], l_i[4], o[4][8];
    #pragma unroll
    for (int i = 0; i < 4; i++) {
        m_i[i] = -1e30f; l_i[i] = 0.f;
        #pragma unroll
        for (int c = 0; c < 8; c++) o[i][c] = 0.f;
    }

    for (int kb = 0; kb < SEQ; kb += 64) {
        __syncthreads();  // previous PV done reading ks
        // load K tile
        #pragma unroll
        for (int i = 0; i < 8; i++) {
            int vid = t + i * 256;
            int row = vid >> 5;
            int c4  = (vid & 31) * 4;
            float4 v = ld4(g_qkv + (size_t)(kb + row) * TD + DIM + h * HD + c4);
            float* d = ks + row * QK_STRIDE + c4;
            d[0] = v.x; d[1] = v.y; d[2] = v.z; d[3] = v.w;
        }
        if (t < 64) sk[t] = seg[kb + t];
        __syncthreads();

        // scores 64x64 (4x4 per thread, strided mapping)
        float s[4][4];
        #pragma unroll
        for (int i = 0; i < 4; i++)
            #pragma unroll
            for (int j = 0; j < 4; j++) s[i][j] = 0.f;

        #pragma unroll 4
        for (int kk = 0; kk < HD; kk++) {
            float af[4], bf[4];
            #pragma unroll
            for (int i = 0; i < 4; i++) af[i] = qs[(ty + 16 * i) * QK_STRIDE + kk];
            #pragma unroll
            for (int j = 0; j < 4; j++) bf[j] = ks[(tx + 16 * j) * QK_STRIDE + kk];
            #pragma unroll
            for (int i = 0; i < 4; i++)
                #pragma unroll
                for (int j = 0; j < 4; j++)
                    s[i][j] += af[i] * bf[j];
        }

        // mask + online softmax
        #pragma unroll
        for (int i = 0; i < 4; i++) {
            int r = ty + 16 * i;
            int sgq = sq[r];
            float rm = -1e30f;
            #pragma unroll
            for (int j = 0; j < 4; j++) {
                s[i][j] += (sgq == sk[tx + 16 * j]) ? 1.0f : 0.0f;
                rm = fmaxf(rm, s[i][j]);
            }
            #pragma unroll
            for (int off = 8; off > 0; off >>= 1)
                rm = fmaxf(rm, __shfl_xor_sync(0xffffffffu, rm, off));
            float mnew = fmaxf(m_i[i], rm);
            float corr = __expf(m_i[i] - mnew);
            m_i[i] = mnew;
            float rsum = 0.f;
            #pragma unroll
            for (int j = 0; j < 4; j++) {
                s[i][j] = __expf(s[i][j] - mnew);
                rsum += s[i][j];
            }
            #pragma unroll
            for (int off = 8; off > 0; off >>= 1)
                rsum += __shfl_xor_sync(0xffffffffu, rsum, off);
            l_i[i] = l_i[i] * corr + rsum;
            #pragma unroll
            for (int c = 0; c < 8; c++) o[i][c] *= corr;
            #pragma unroll
            for (int j = 0; j < 4; j++)
                ps[r * P_STRIDE + tx + 16 * j] = s[i][j];
        }
        __syncthreads();  // scores done reading ks; ps written

        // load V tile over ks
        #pragma unroll
        for (int i = 0; i < 8; i++) {
            int vid = t + i * 256;
            int row = vid >> 5;
            int c4  = (vid & 31) * 4;
            float4 v = ld4(g_qkv + (size_t)(kb + row) * TD + 2 * DIM + h * HD + c4);
            float* d = ks + row * QK_STRIDE + c4;
            d[0] = v.x; d[1] = v.y; d[2] = v.z; d[3] = v.w;
        }
        __syncthreads();

        // O += P @ V
        #pragma unroll 4
        for (int j2 = 0; j2 < 64; j2++) {
            float pv[4], vv[8];
            #pragma unroll
            for (int i = 0; i < 4; i++) pv[i] = ps[(ty + 16 * i) * P_STRIDE + j2];
            #pragma unroll
            for (int c = 0; c < 8; c++) vv[c] = ks[j2 * QK_STRIDE + tx + 16 * c];
            #pragma unroll
            for (int i = 0; i < 4; i++)
                #pragma unroll
                for (int c = 0; c < 8; c++)
                    o[i][c] += pv[i] * vv[c];
        }
    }

    // normalize and write [s, h*HD + d]
    #pragma unroll
    for (int i = 0; i < 4; i++) {
        float inv = 1.0f / l_i[i];
        size_t rbase = (size_t)(q0 + ty + 16 * i) * DIM + h * HD;
        #pragma unroll
        for (int c = 0; c < 8; c++)
            g_attn[rbase + tx + 16 * c] = o[i][c] * inv;
    }
}

// ======================= launcher =======================
extern "C" void kernel_launch(void* const* d_in, const int* in_sizes, int n_in,
                              void* d_out, int out_size)
{
    const float* byte_repr = (const float*)d_in[0];
    const int*   categories= (const int*)  d_in[1];
    const int*   cse       = (const int*)  d_in[2];
    const int*   comb      = (const int*)  d_in[3];
    const int*   seg_ids   = (const int*)  d_in[4];
    const float* cat_emb   = (const float*)d_in[5];
    const float* case_emb  = (const float*)d_in[6];
    const float* comb_emb  = (const float*)d_in[7];
    const float* ln_g      = (const float*)d_in[8];
    const float* ln_b      = (const float*)d_in[9];
    const float* in_w      = (const float*)d_in[10];
    const float* in_b      = (const float*)d_in[11];
    const float* out_w     = (const float*)d_in[12];
    const float* out_b     = (const float*)d_in[13];
    float* out = (float*)d_out;

    float *p_xn, *p_qkv, *p_attn;
    cudaGetSymbolAddress((void**)&p_xn,   g_xn);
    cudaGetSymbolAddress((void**)&p_qkv,  g_qkv);
    cudaGetSymbolAddress((void**)&p_attn, g_attn);

    cudaFuncSetAttribute(k_attn, cudaFuncAttributeMaxDynamicSharedMemorySize, ATTN_SMEM);

    // 1) fused embed + LN
    k_embed_ln<<<SEQ, 256>>>(byte_repr, categories, cse, comb,
                             cat_emb, case_emb, comb_emb, ln_g, ln_b);

    // 2) QKV projection: [S,3D] = xn @ in_w^T + in_b
    dim3 gq(TD / 128, SEQ / 128);
    k_sgemm_nt<<<gq, 256>>>(p_xn, in_w, in_b, nullptr, p_qkv, SEQ, TD, DIM);

    // 3) attention
    dim3 ga(SEQ / 64, NH);
    k_attn<<<ga, 256, ATTN_SMEM>>>(seg_ids);

    // 4) out projection + residual: out = xn + attn @ out_w^T + out_b
    dim3 go(DIM / 128, SEQ / 128);
    k_sgemm_nt<<<go, 256>>>(p_attn, out_w, out_b, p_xn, out, SEQ, DIM, DIM);
}

// round 2
// speedup vs baseline: 1.3795x; 1.3795x over previous
#include <cuda_runtime.h>
#include <cstdint>

#define SEQ 2048
#define DIM 2048
#define NH  16
#define HD  128
#define TD  (3*DIM)
#define LN_EPS 1e-5f

// ---------------- scratch (static device globals; no allocation) ----------------
__device__ float g_xn[(size_t)SEQ*DIM];     // 16 MB  LayerNorm output (also residual)
__device__ float g_qkv[(size_t)SEQ*TD];     // 48 MB  QKV projection output
__device__ float g_attn[(size_t)SEQ*DIM];   // 16 MB  attention output [S, H*HD]

__device__ __forceinline__ float4 ld4(const float* p){ return *(const float4*)p; }

// ---------------- f32x2 packed helpers ----------------
typedef unsigned long long u64t;

__device__ __forceinline__ u64t pk(float lo, float hi){
    u64t r; asm("mov.b64 %0, {%1,%2};" : "=l"(r) : "f"(lo), "f"(hi)); return r;
}
__device__ __forceinline__ float2 upk(u64t v){
    float2 r; asm("mov.b64 {%0,%1}, %2;" : "=f"(r.x), "=f"(r.y) : "l"(v)); return r;
}
__device__ __forceinline__ void fma2(u64t& d, u64t a, u64t b){
    asm("fma.rn.f32x2 %0, %1, %2, %0;" : "+l"(d) : "l"(a), "l"(b));
}
__device__ __forceinline__ void mul2(u64t& d, u64t a){
    asm("mul.rn.f32x2 %0, %0, %1;" : "+l"(d) : "l"(a));
}

// ======================= kernel 1: fused embed + LayerNorm =======================
__global__ void __launch_bounds__(256) k_embed_ln(
    const float* __restrict__ byte_repr,
    const int*   __restrict__ cats,
    const int*   __restrict__ cse,
    const int*   __restrict__ comb,
    const float* __restrict__ cat_emb,
    const float* __restrict__ case_emb,
    const float* __restrict__ comb_emb,
    const float* __restrict__ g,
    const float* __restrict__ b)
{
    int s = blockIdx.x;
    int t = threadIdx.x;
    int lane = t & 31, wid = t >> 5;
    int c0 = t * 4;
    int c1 = 1024 + t * 4;

    size_t catb = (size_t)cats[s] * DIM;
    size_t cab  = (size_t)cse[s]  * DIM;
    size_t cob  = (size_t)comb[s] * DIM;
    const float* base = byte_repr + (size_t)s * DIM;

    float x[8];
    {
        float4 a = ld4(base + c0), e = ld4(cat_emb + catb + c0);
        float4 f = ld4(case_emb + cab + c0), h = ld4(comb_emb + cob + c0);
        x[0] = a.x + e.x + f.x + h.x;  x[1] = a.y + e.y + f.y + h.y;
        x[2] = a.z + e.z + f.z + h.z;  x[3] = a.w + e.w + f.w + h.w;
    }
    {
        float4 a = ld4(base + c1), e = ld4(cat_emb + catb + c1);
        float4 f = ld4(case_emb + cab + c1), h = ld4(comb_emb + cob + c1);
        x[4] = a.x + e.x + f.x + h.x;  x[5] = a.y + e.y + f.y + h.y;
        x[6] = a.z + e.z + f.z + h.z;  x[7] = a.w + e.w + f.w + h.w;
    }

    __shared__ float red[8];
    __shared__ float s_bcast;

    float sum = 0.f;
    #pragma unroll
    for (int i = 0; i < 8; i++) sum += x[i];
    #pragma unroll
    for (int o = 16; o > 0; o >>= 1) sum += __shfl_xor_sync(0xffffffffu, sum, o);
    if (lane == 0) red[wid] = sum;
    __syncthreads();
    if (t == 0) {
        float v = 0.f;
        #pragma unroll
        for (int i = 0; i < 8; i++) v += red[i];
        s_bcast = v * (1.0f / DIM);
    }
    __syncthreads();
    float mu = s_bcast;
    __syncthreads();

    float sq = 0.f;
    #pragma unroll
    for (int i = 0; i < 8; i++) { float d = x[i] - mu; sq += d * d; }
    #pragma unroll
    for (int o = 16; o > 0; o >>= 1) sq += __shfl_xor_sync(0xffffffffu, sq, o);
    if (lane == 0) red[wid] = sq;
    __syncthreads();
    if (t == 0) {
        float v = 0.f;
        #pragma unroll
        for (int i = 0; i < 8; i++) v += red[i];
        s_bcast = rsqrtf(v * (1.0f / DIM) + LN_EPS);
    }
    __syncthreads();
    float rs = s_bcast;

    float* dst = g_xn + (size_t)s * DIM;
    {
        float4 gg = ld4(g + c0), bb = ld4(b + c0);
        float4 o;
        o.x = (x[0] - mu) * rs * gg.x + bb.x;
        o.y = (x[1] - mu) * rs * gg.y + bb.y;
        o.z = (x[2] - mu) * rs * gg.z + bb.z;
        o.w = (x[3] - mu) * rs * gg.w + bb.w;
        *(float4*)(dst + c0) = o;
    }
    {
        float4 gg = ld4(g + c1), bb = ld4(b + c1);
        float4 o;
        o.x = (x[4] - mu) * rs * gg.x + bb.x;
        o.y = (x[5] - mu) * rs * gg.y + bb.y;
        o.z = (x[6] - mu) * rs * gg.z + bb.z;
        o.w = (x[7] - mu) * rs * gg.w + bb.w;
        *(float4*)(dst + c1) = o;
    }
}

// ================= kernel 2/4: SGEMM-NT with packed f32x2 =================
// C[m,n] = sum_k A[m,k]*B[n,k] + bias[n] (+resid). BM=BN=128, BK=16, 256 thr.
// Per-thread: rows {ty*4+0..3, 64+ty*4+0..3}, cols {tx*4+0..3, 64+tx*4+0..3}.
// acc[i][j]: i = row index (0..7), j = n-pair index (0..3), each a f32x2.
__global__ void __launch_bounds__(256) k_sgemm_nt(
    const float* __restrict__ A, const float* __restrict__ B,
    const float* __restrict__ bias, const float* __restrict__ resid,
    float* __restrict__ C, int M, int N, int K)
{
    __shared__ float As[16][132];
    __shared__ float Bs[16][132];

    int bm = blockIdx.y * 128;
    int bn = blockIdx.x * 128;
    int t = threadIdx.x;
    int tx = t & 15, ty = t >> 4;

    u64t acc[8][4];
    #pragma unroll
    for (int i = 0; i < 8; i++)
        #pragma unroll
        for (int j = 0; j < 4; j++) acc[i][j] = 0ull;

    for (int kt = 0; kt < K; kt += 16) {
        #pragma unroll
        for (int i = 0; i < 2; i++) {
            int vid = t + i * 256;
            int row = vid >> 2;
            int c4  = (vid & 3) * 4;
            float4 a = ld4(A + (size_t)(bm + row) * K + kt + c4);
            As[c4 + 0][row] = a.x; As[c4 + 1][row] = a.y;
            As[c4 + 2][row] = a.z; As[c4 + 3][row] = a.w;
            float4 bb = ld4(B + (size_t)(bn + row) * K + kt + c4);
            Bs[c4 + 0][row] = bb.x; Bs[c4 + 1][row] = bb.y;
            Bs[c4 + 2][row] = bb.z; Bs[c4 + 3][row] = bb.w;
        }
        __syncthreads();

        #pragma unroll
        for (int k = 0; k < 16; k++) {
            float4 a0 = *(const float4*)&As[k][ty * 4];
            float4 a1 = *(const float4*)&As[k][64 + ty * 4];
            float4 b0 = *(const float4*)&Bs[k][tx * 4];
            float4 b1 = *(const float4*)&Bs[k][64 + tx * 4];
            u64t bp[4] = { pk(b0.x, b0.y), pk(b0.z, b0.w),
                           pk(b1.x, b1.y), pk(b1.z, b1.w) };
            u64t ap[8] = { pk(a0.x, a0.x), pk(a0.y, a0.y), pk(a0.z, a0.z), pk(a0.w, a0.w),
                           pk(a1.x, a1.x), pk(a1.y, a1.y), pk(a1.z, a1.z), pk(a1.w, a1.w) };
            #pragma unroll
            for (int i = 0; i < 8; i++)
                #pragma unroll
                for (int j = 0; j < 4; j++)
                    fma2(acc[i][j], ap[i], bp[j]);
        }
        __syncthreads();
    }

    float4 bias0 = ld4(bias + bn + tx * 4);
    float4 bias1 = ld4(bias + bn + 64 + tx * 4);

    #pragma unroll
    for (int i = 0; i < 8; i++) {
        int m = bm + ((i < 4) ? (ty * 4 + i) : (64 + ty * 4 + i - 4));
        float2 p0 = upk(acc[i][0]), p1 = upk(acc[i][1]);
        float2 p2 = upk(acc[i][2]), p3 = upk(acc[i][3]);
        float4 v0 = { p0.x + bias0.x, p0.y + bias0.y, p1.x + bias0.z, p1.y + bias0.w };
        float4 v1 = { p2.x + bias1.x, p2.y + bias1.y, p3.x + bias1.z, p3.y + bias1.w };
        size_t rb = (size_t)m * N;
        if (resid) {
            float4 r0 = ld4(resid + rb + bn + tx * 4);
            float4 r1 = ld4(resid + rb + bn + 64 + tx * 4);
            v0.x += r0.x; v0.y += r0.y; v0.z += r0.z; v0.w += r0.w;
            v1.x += r1.x; v1.y += r1.y; v1.z += r1.z; v1.w += r1.w;
        }
        *(float4*)(C + rb + bn + tx * 4) = v0;
        *(float4*)(C + rb + bn + 64 + tx * 4) = v1;
    }
}

// ======================= kernel 3: flash-style attention (f32x2) =======================
// grid (SEQ/64, NH), 256 threads (16x16). BQ=BK=64. Online softmax.
#define QK_STRIDE 132
#define P_STRIDE   68
#define ATTN_SMEM ((64*QK_STRIDE*2 + 64*P_STRIDE) * 4 + 128 * 4)

__global__ void __launch_bounds__(256) k_attn(const int* __restrict__ seg)
{
    extern __shared__ float sm[];
    float* qs = sm;                         // [64][132]
    float* ks = qs + 64 * QK_STRIDE;        // [64][132]  (K tile, then reused for V)
    float* ps = ks + 64 * QK_STRIDE;        // [64][68]
    int*   sq = (int*)(ps + 64 * P_STRIDE); // [64]
    int*   sk = sq + 64;                    // [64]

    int q0 = blockIdx.x * 64;
    int h  = blockIdx.y;
    int t = threadIdx.x;
    int tx = t & 15, ty = t >> 4;
    const float scale = 0.08838834764831845f; // 1/sqrt(128)

    // load Q tile (pre-scaled)
    #pragma unroll
    for (int i = 0; i < 8; i++) {
        int vid = t + i * 256;
        int row = vid >> 5;
        int c4  = (vid & 31) * 4;
        float4 v = ld4(g_qkv + (size_t)(q0 + row) * TD + h * HD + c4);
        float* d = qs + row * QK_STRIDE + c4;
        d[0] = v.x * scale; d[1] = v.y * scale; d[2] = v.z * scale; d[3] = v.w * scale;
    }
    if (t < 64) sq[t] = seg[q0 + t];

    // o accumulator: rows ty+16i (i 0..3), cols {tx*4+0..3, 64+tx*4+0..3} as 4 f32x2
    float m_i[4], l_i[4];
    u64t o2[4][4];
    #pragma unroll
    for (int i = 0; i < 4; i++) {
        m_i[i] = -1e30f; l_i[i] = 0.f;
        #pragma unroll
        for (int c = 0; c < 4; c++) o2[i][c] = 0ull;
    }

    for (int kb = 0; kb < SEQ; kb += 64) {
        __syncthreads();  // previous PV done reading ks
        // load K tile
        #pragma unroll
        for (int i = 0; i < 8; i++) {
            int vid = t + i * 256;
            int row = vid >> 5;
            int c4  = (vid & 31) * 4;
            float4 v = ld4(g_qkv + (size_t)(kb + row) * TD + DIM + h * HD + c4);
            float* d = ks + row * QK_STRIDE + c4;
            d[0] = v.x; d[1] = v.y; d[2] = v.z; d[3] = v.w;
        }
        if (t < 64) sk[t] = seg[kb + t];
        __syncthreads();

        // scores 64x64 (4x4 per thread); k-parity pair accumulation in f32x2
        u64t s2[4][4];
        #pragma unroll
        for (int i = 0; i < 4; i++)
            #pragma unroll
            for (int j = 0; j < 4; j++) s2[i][j] = 0ull;

        #pragma unroll 8
        for (int kk = 0; kk < HD; kk += 2) {
            u64t a2[4], b2[4];
            #pragma unroll
            for (int i = 0; i < 4; i++) {
                float2 v = *(const float2*)&qs[(ty + 16 * i) * QK_STRIDE + kk];
                a2[i] = pk(v.x, v.y);
            }
            #pragma unroll
            for (int j = 0; j < 4; j++) {
                float2 v = *(const float2*)&ks[(tx + 16 * j) * QK_STRIDE + kk];
                b2[j] = pk(v.x, v.y);
            }
            #pragma unroll
            for (int i = 0; i < 4; i++)
                #pragma unroll
                for (int j = 0; j < 4; j++)
                    fma2(s2[i][j], a2[i], b2[j]);
        }

        // mask + online softmax
        #pragma unroll
        for (int i = 0; i < 4; i++) {
            int r = ty + 16 * i;
            int sgq = sq[r];
            float s[4];
            float rm = -1e30f;
            #pragma unroll
            for (int j = 0; j < 4; j++) {
                float2 v = upk(s2[i][j]);
                s[j] = v.x + v.y + ((sgq == sk[tx + 16 * j]) ? 1.0f : 0.0f);
                rm = fmaxf(rm, s[j]);
            }
            #pragma unroll
            for (int off = 8; off > 0; off >>= 1)
                rm = fmaxf(rm, __shfl_xor_sync(0xffffffffu, rm, off));
            float mnew = fmaxf(m_i[i], rm);
            float corr = __expf(m_i[i] - mnew);
            m_i[i] = mnew;
            float rsum = 0.f;
            #pragma unroll
            for (int j = 0; j < 4; j++) {
                s[j] = __expf(s[j] - mnew);
                rsum += s[j];
            }
            #pragma unroll
            for (int off = 8; off > 0; off >>= 1)
                rsum += __shfl_xor_sync(0xffffffffu, rsum, off);
            l_i[i] = l_i[i] * corr + rsum;
            u64t corr2 = pk(corr, corr);
            #pragma unroll
            for (int c = 0; c < 4; c++) mul2(o2[i][c], corr2);
            #pragma unroll
            for (int j = 0; j < 4; j++)
                ps[r * P_STRIDE + tx + 16 * j] = s[j];
        }
        __syncthreads();  // scores done reading ks; ps written

        // load V tile over ks
        #pragma unroll
        for (int i = 0; i < 8; i++) {
            int vid = t + i * 256;
            int row = vid >> 5;
            int c4  = (vid & 31) * 4;
            float4 v = ld4(g_qkv + (size_t)(kb + row) * TD + 2 * DIM + h * HD + c4);
            float* d = ks + row * QK_STRIDE + c4;
            d[0] = v.x; d[1] = v.y; d[2] = v.z; d[3] = v.w;
        }
        __syncthreads();

        // O += P @ V  (V read as contiguous col-pairs, P dup'd)
        #pragma unroll 4
        for (int j2 = 0; j2 < 64; j2++) {
            float4 v0 = *(const float4*)&ks[j2 * QK_STRIDE + tx * 4];
            float4 v1 = *(const float4*)&ks[j2 * QK_STRIDE + 64 + tx * 4];
            u64t vp[4] = { pk(v0.x, v0.y), pk(v0.z, v0.w),
                           pk(v1.x, v1.y), pk(v1.z, v1.w) };
            u64t pd[4];
            #pragma unroll
            for (int i = 0; i < 4; i++) {
                float p = ps[(ty + 16 * i) * P_STRIDE + j2];
                pd[i] = pk(p, p);
            }
            #pragma unroll
            for (int i = 0; i < 4; i++)
                #pragma unroll
                for (int c = 0; c < 4; c++)
                    fma2(o2[i][c], pd[i], vp[c]);
        }
    }

    // normalize and write [s, h*HD + d]; cols {tx*4..+3, 64+tx*4..+3}
    #pragma unroll
    for (int i = 0; i < 4; i++) {
        float inv = 1.0f / l_i[i];
        size_t rbase = (size_t)(q0 + ty + 16 * i) * DIM + h * HD;
        float2 p0 = upk(o2[i][0]), p1 = upk(o2[i][1]);
        float2 p2 = upk(o2[i][2]), p3 = upk(o2[i][3]);
        float4 w0 = { p0.x * inv, p0.y * inv, p1.x * inv, p1.y * inv };
        float4 w1 = { p2.x * inv, p2.y * inv, p3.x * inv, p3.y * inv };
        *(float4*)(g_attn + rbase + tx * 4) = w0;
        *(float4*)(g_attn + rbase + 64 + tx * 4) = w1;
    }
}

// ======================= launcher =======================
extern "C" void kernel_launch(void* const* d_in, const int* in_sizes, int n_in,
                              void* d_out, int out_size)
{
    const float* byte_repr = (const float*)d_in[0];
    const int*   categories= (const int*)  d_in[1];
    const int*   cse       = (const int*)  d_in[2];
    const int*   comb      = (const int*)  d_in[3];
    const int*   seg_ids   = (const int*)  d_in[4];
    const float* cat_emb   = (const float*)d_in[5];
    const float* case_emb  = (const float*)d_in[6];
    const float* comb_emb  = (const float*)d_in[7];
    const float* ln_g      = (const float*)d_in[8];
    const float* ln_b      = (const float*)d_in[9];
    const float* in_w      = (const float*)d_in[10];
    const float* in_b      = (const float*)d_in[11];
    const float* out_w     = (const float*)d_in[12];
    const float* out_b     = (const float*)d_in[13];
    float* out = (float*)d_out;

    float *p_xn, *p_qkv, *p_attn;
    cudaGetSymbolAddress((void**)&p_xn,   g_xn);
    cudaGetSymbolAddress((void**)&p_qkv,  g_qkv);
    cudaGetSymbolAddress((void**)&p_attn, g_attn);

    cudaFuncSetAttribute(k_attn, cudaFuncAttributeMaxDynamicSharedMemorySize, ATTN_SMEM);

    // 1) fused embed + LN
    k_embed_ln<<<SEQ, 256>>>(byte_repr, categories, cse, comb,
                             cat_emb, case_emb, comb_emb, ln_g, ln_b);

    // 2) QKV projection: [S,3D] = xn @ in_w^T + in_b
    dim3 gq(TD / 128, SEQ / 128);
    k_sgemm_nt<<<gq, 256>>>(p_xn, in_w, in_b, nullptr, p_qkv, SEQ, TD, DIM);

    // 3) attention
    dim3 ga(SEQ / 64, NH);
    k_attn<<<ga, 256, ATTN_SMEM>>>(seg_ids);

    // 4) out projection + residual: out = xn + attn @ out_w^T + out_b
    dim3 go(DIM / 128, SEQ / 128);
    k_sgemm_nt<<<go, 256>>>(p_attn, out_w, out_b, p_xn, out, SEQ, DIM, DIM);
}

// round 4
// speedup vs baseline: 2.6189x; 1.8985x over previous
#include <cuda_runtime.h>
#include <cuda_fp16.h>
#include <cstdint>

#define SEQ 2048
#define DIM 2048
#define NH  16
#define HD  128
#define TD  (3*DIM)
#define LN_EPS 1e-5f

// ---------------- scratch (static device globals; no allocation) ----------------
__device__ float  g_xn[(size_t)SEQ*DIM];      // LayerNorm output fp32 (residual)
__device__ float  g_qkv[(size_t)SEQ*TD];      // QKV projection output fp32
__device__ __half g_xn_h[(size_t)SEQ*DIM];    // f16 copies for tensor-core GEMMs
__device__ __half g_attn_h[(size_t)SEQ*DIM];
__device__ __half g_w1_h[(size_t)TD*DIM];
__device__ __half g_w2_h[(size_t)DIM*DIM];

__device__ __forceinline__ float4 ld4(const float* p){ return *(const float4*)p; }

// ---------------- f32x2 packed helpers (attention) ----------------
typedef unsigned long long u64t;
__device__ __forceinline__ u64t pk(float lo, float hi){
    u64t r; asm("mov.b64 %0, {%1,%2};" : "=l"(r) : "f"(lo), "f"(hi)); return r;
}
__device__ __forceinline__ float2 upk(u64t v){
    float2 r; asm("mov.b64 {%0,%1}, %2;" : "=f"(r.x), "=f"(r.y) : "l"(v)); return r;
}
__device__ __forceinline__ void fma2(u64t& d, u64t a, u64t b){
    asm("fma.rn.f32x2 %0, %1, %2, %0;" : "+l"(d) : "l"(a), "l"(b));
}
__device__ __forceinline__ void mul2(u64t& d, u64t a){
    asm("mul.rn.f32x2 %0, %0, %1;" : "+l"(d) : "l"(a));
}

// ---------------- HMMA helpers ----------------
__device__ __forceinline__ uint32_t smem_u32(const void* p){
    uint32_t a; asm("{ .reg .u64 t; cvta.to.shared.u64 t, %1; cvt.u32.u64 %0, t; }" : "=r"(a) : "l"(p)); return a;
}
__device__ __forceinline__ void ldsm4(uint32_t& r0, uint32_t& r1, uint32_t& r2, uint32_t& r3, uint32_t a){
    asm volatile("ldmatrix.sync.aligned.m8n8.x4.shared.b16 {%0,%1,%2,%3}, [%4];"
                 : "=r"(r0), "=r"(r1), "=r"(r2), "=r"(r3) : "r"(a));
}
__device__ __forceinline__ void mma16816(float* c, uint32_t a0, uint32_t a1, uint32_t a2, uint32_t a3,
                                         uint32_t b0, uint32_t b1){
    asm volatile("mma.sync.aligned.m16n8k16.row.col.f32.f16.f16.f32 "
                 "{%0,%1,%2,%3}, {%4,%5,%6,%7}, {%8,%9}, {%0,%1,%2,%3};"
                 : "+f"(c[0]), "+f"(c[1]), "+f"(c[2]), "+f"(c[3])
                 : "r"(a0), "r"(a1), "r"(a2), "r"(a3), "r"(b0), "r"(b1));
}
__device__ __forceinline__ void cpasync16(uint32_t dst, const void* src){
    asm volatile("cp.async.cg.shared.global [%0], [%1], 16;" :: "r"(dst), "l"(src));
}

// ================= HMMA f16 GEMM-NT: C[m,n] = sum_k A[m,k]*B[n,k] + bias[n] (+resid) =================
// BM=BN=128, BK=32, 256 threads (8 warps as 2x4), warp tile 64x32, mma m16n8k16.
#define BK 32
#define TSTR 40   // smem row stride in f16 (80B: ldmatrix conflict-free mod 128)

__global__ void __launch_bounds__(256) h_gemm(
    const __half* __restrict__ A, const __half* __restrict__ B,
    const float* __restrict__ bias, const float* __restrict__ resid,
    float* __restrict__ C, int M, int N, int K)
{
    __shared__ __half As[2][128 * TSTR];
    __shared__ __half Bs[2][128 * TSTR];

    int t = threadIdx.x, lane = t & 31, w = t >> 5;
    int bm = blockIdx.y * 128, bn = blockIdx.x * 128;
    int wm = (w >> 2) * 64, wn = (w & 3) * 32;

    uint32_t as_base[2] = { smem_u32(As[0]), smem_u32(As[1]) };
    uint32_t bs_base[2] = { smem_u32(Bs[0]), smem_u32(Bs[1]) };

    // cp.async mapping: 512 chunks of 16B per tile (128 rows x 4), 2 per thread
    int r0c = t >> 1;            // row for chunk set: vid = t + i*256
    (void)r0c;

    // ldmatrix per-lane offsets (element units within tile)
    int a_row = wm + (lane & 7) + ((lane & 8) ? 8 : 0);
    int a_kof = (lane & 16) ? 8 : 0;
    int b_row = wn + (lane & 7) + ((lane & 16) ? 8 : 0);
    int b_kof = (lane & 8) ? 8 : 0;

    float acc[4][4][4];
    #pragma unroll
    for (int i = 0; i < 4; i++)
        #pragma unroll
        for (int j = 0; j < 4; j++)
            #pragma unroll
            for (int c = 0; c < 4; c++) acc[i][j][c] = 0.f;

    int niter = K / BK;

    // prologue: load tile 0
    {
        #pragma unroll
        for (int i = 0; i < 2; i++) {
            int vid = t + i * 256;
            int row = vid >> 2, c = vid & 3;
            cpasync16(as_base[0] + (row * TSTR + c * 8) * 2, A + (size_t)(bm + row) * K + c * 8);
            cpasync16(bs_base[0] + (row * TSTR + c * 8) * 2, B + (size_t)(bn + row) * K + c * 8);
        }
        asm volatile("cp.async.commit_group;" ::: "memory");
    }

    for (int kt = 0; kt < niter; kt++) {
        int buf = kt & 1;
        if (kt + 1 < niter) {
            int nb = buf ^ 1;
            const __half* Ak = A + (size_t)(kt + 1) * BK;
            const __half* Bk = B + (size_t)(kt + 1) * BK;
            #pragma unroll
            for (int i = 0; i < 2; i++) {
                int vid = t + i * 256;
                int row = vid >> 2, c = vid & 3;
                cpasync16(as_base[nb] + (row * TSTR + c * 8) * 2, Ak + (size_t)(bm + row) * K + c * 8);
                cpasync16(bs_base[nb] + (row * TSTR + c * 8) * 2, Bk + (size_t)(bn + row) * K + c * 8);
            }
            asm volatile("cp.async.commit_group;" ::: "memory");
            asm volatile("cp.async.wait_group 1;" ::: "memory");
        } else {
            asm volatile("cp.async.wait_group 0;" ::: "memory");
        }
        __syncthreads();

        uint32_t abase = as_base[buf], bbase = bs_base[buf];
        #pragma unroll
        for (int ks = 0; ks < 2; ks++) {
            uint32_t a[4][4], b[2][4];
            #pragma unroll
            for (int i = 0; i < 4; i++) {
                uint32_t addr = abase + (((a_row + i * 16) * TSTR) + ks * 16 + a_kof) * 2;
                ldsm4(a[i][0], a[i][1], a[i][2], a[i][3], addr);
            }
            #pragma unroll
            for (int p = 0; p < 2; p++) {
                uint32_t addr = bbase + (((b_row + p * 16) * TSTR) + ks * 16 + b_kof) * 2;
                ldsm4(b[p][0], b[p][1], b[p][2], b[p][3], addr);
            }
            #pragma unroll
            for (int i = 0; i < 4; i++) {
                #pragma unroll
                for (int j = 0; j < 4; j++) {
                    int p = j >> 1;
                    uint32_t bb0 = (j & 1) ? b[p][2] : b[p][0];
                    uint32_t bb1 = (j & 1) ? b[p][3] : b[p][1];
                    mma16816(acc[i][j], a[i][0], a[i][1], a[i][2], a[i][3], bb0, bb1);
                }
            }
        }
        __syncthreads();
    }

    // epilogue
    int mrow = bm + wm + (lane >> 2);
    int ncol = bn + wn + 2 * (lane & 3);
    #pragma unroll
    for (int i = 0; i < 4; i++) {
        #pragma unroll
        for (int j = 0; j < 4; j++) {
            int n0 = ncol + j * 8;
            float b0 = bias[n0], b1 = bias[n0 + 1];
            int m0 = mrow + i * 16;
            size_t rb0 = (size_t)m0 * N + n0;
            size_t rb1 = (size_t)(m0 + 8) * N + n0;
            float2 v0 = { acc[i][j][0] + b0, acc[i][j][1] + b1 };
            float2 v1 = { acc[i][j][2] + b0, acc[i][j][3] + b1 };
            if (resid) {
                float2 r0 = *(const float2*)(resid + rb0);
                float2 r1 = *(const float2*)(resid + rb1);
                v0.x += r0.x; v0.y += r0.y; v1.x += r1.x; v1.y += r1.y;
            }
            *(float2*)(C + rb0) = v0;
            *(float2*)(C + rb1) = v1;
        }
    }
}

// ======================= fp32 -> f16 convert =======================
__global__ void __launch_bounds__(256) k_conv_h(const float* __restrict__ src,
                                               __half* __restrict__ dst, int n8)
{
    int i = blockIdx.x * 256 + threadIdx.x;
    if (i >= n8) return;
    float4 a = ld4(src + (size_t)i * 8);
    float4 b = ld4(src + (size_t)i * 8 + 4);
    __half2 h[4];
    h[0] = __floats2half2_rn(a.x, a.y);
    h[1] = __floats2half2_rn(a.z, a.w);
    h[2] = __floats2half2_rn(b.x, b.y);
    h[3] = __floats2half2_rn(b.z, b.w);
    *(uint4*)(dst + (size_t)i * 8) = *(uint4*)h;
}

// ======================= kernel 1: fused embed + LayerNorm (+f16 copy) =======================
__global__ void __launch_bounds__(256) k_embed_ln(
    const float* __restrict__ byte_repr,
    const int*   __restrict__ cats,
    const int*   __restrict__ cse,
    const int*   __restrict__ comb,
    const float* __restrict__ cat_emb,
    const float* __restrict__ case_emb,
    const float* __restrict__ comb_emb,
    const float* __restrict__ g,
    const float* __restrict__ b)
{
    int s = blockIdx.x;
    int t = threadIdx.x;
    int lane = t & 31, wid = t >> 5;
    int c0 = t * 4;
    int c1 = 1024 + t * 4;

    size_t catb = (size_t)cats[s] * DIM;
    size_t cab  = (size_t)cse[s]  * DIM;
    size_t cob  = (size_t)comb[s] * DIM;
    const float* base = byte_repr + (size_t)s * DIM;

    float x[8];
    {
        float4 a = ld4(base + c0), e = ld4(cat_emb + catb + c0);
        float4 f = ld4(case_emb + cab + c0), h = ld4(comb_emb + cob + c0);
        x[0] = a.x + e.x + f.x + h.x;  x[1] = a.y + e.y + f.y + h.y;
        x[2] = a.z + e.z + f.z + h.z;  x[3] = a.w + e.w + f.w + h.w;
    }
    {
        float4 a = ld4(base + c1), e = ld4(cat_emb + catb + c1);
        float4 f = ld4(case_emb + cab + c1), h = ld4(comb_emb + cob + c1);
        x[4] = a.x + e.x + f.x + h.x;  x[5] = a.y + e.y + f.y + h.y;
        x[6] = a.z + e.z + f.z + h.z;  x[7] = a.w + e.w + f.w + h.w;
    }

    __shared__ float red[8];
    __shared__ float s_bcast;

    float sum = 0.f;
    #pragma unroll
    for (int i = 0; i < 8; i++) sum += x[i];
    #pragma unroll
    for (int o = 16; o > 0; o >>= 1) sum += __shfl_xor_sync(0xffffffffu, sum, o);
    if (lane == 0) red[wid] = sum;
    __syncthreads();
    if (t == 0) {
        float v = 0.f;
        #pragma unroll
        for (int i = 0; i < 8; i++) v += red[i];
        s_bcast = v * (1.0f / DIM);
    }
    __syncthreads();
    float mu = s_bcast;
    __syncthreads();

    float sq = 0.f;
    #pragma unroll
    for (int i = 0; i < 8; i++) { float d = x[i] - mu; sq += d * d; }
    #pragma unroll
    for (int o = 16; o > 0; o >>= 1) sq += __shfl_xor_sync(0xffffffffu, sq, o);
    if (lane == 0) red[wid] = sq;
    __syncthreads();
    if (t == 0) {
        float v = 0.f;
        #pragma unroll
        for (int i = 0; i < 8; i++) v += red[i];
        s_bcast = rsqrtf(v * (1.0f / DIM) + LN_EPS);
    }
    __syncthreads();
    float rs = s_bcast;

    float* dst = g_xn + (size_t)s * DIM;
    __half* dsth = g_xn_h + (size_t)s * DIM;
    {
        float4 gg = ld4(g + c0), bb = ld4(b + c0);
        float4 o;
        o.x = (x[0] - mu) * rs * gg.x + bb.x;
        o.y = (x[1] - mu) * rs * gg.y + bb.y;
        o.z = (x[2] - mu) * rs * gg.z + bb.z;
        o.w = (x[3] - mu) * rs * gg.w + bb.w;
        *(float4*)(dst + c0) = o;
        __half2 h2[2] = { __floats2half2_rn(o.x, o.y), __floats2half2_rn(o.z, o.w) };
        *(uint2*)(dsth + c0) = *(uint2*)h2;
    }
    {
        float4 gg = ld4(g + c1), bb = ld4(b + c1);
        float4 o;
        o.x = (x[4] - mu) * rs * gg.x + bb.x;
        o.y = (x[5] - mu) * rs * gg.y + bb.y;
        o.z = (x[6] - mu) * rs * gg.z + bb.z;
        o.w = (x[7] - mu) * rs * gg.w + bb.w;
        *(float4*)(dst + c1) = o;
        __half2 h2[2] = { __floats2half2_rn(o.x, o.y), __floats2half2_rn(o.z, o.w) };
        *(uint2*)(dsth + c1) = *(uint2*)h2;
    }
}

// ======================= kernel 3: flash-style attention (f32x2, f16 out) =======================
#define QK_STRIDE 132
#define P_STRIDE   68
#define ATTN_SMEM ((64*QK_STRIDE*2 + 64*P_STRIDE) * 4 + 128 * 4)

__global__ void __launch_bounds__(256) k_attn(const int* __restrict__ seg)
{
    extern __shared__ float sm[];
    float* qs = sm;
    float* ks = qs + 64 * QK_STRIDE;
    float* ps = ks + 64 * QK_STRIDE;
    int*   sq = (int*)(ps + 64 * P_STRIDE);
    int*   sk = sq + 64;

    int q0 = blockIdx.x * 64;
    int h  = blockIdx.y;
    int t = threadIdx.x;
    int tx = t & 15, ty = t >> 4;
    const float scale = 0.08838834764831845f;

    #pragma unroll
    for (int i = 0; i < 8; i++) {
        int vid = t + i * 256;
        int row = vid >> 5;
        int c4  = (vid & 31) * 4;
        float4 v = ld4(g_qkv + (size_t)(q0 + row) * TD + h * HD + c4);
        float* d = qs + row * QK_STRIDE + c4;
        d[0] = v.x * scale; d[1] = v.y * scale; d[2] = v.z * scale; d[3] = v.w * scale;
    }
    if (t < 64) sq[t] = seg[q0 + t];

    float m_i[4], l_i[4];
    u64t o2[4][4];
    #pragma unroll
    for (int i = 0; i < 4; i++) {
        m_i[i] = -1e30f; l_i[i] = 0.f;
        #pragma unroll
        for (int c = 0; c < 4; c++) o2[i][c] = 0ull;
    }

    for (int kb = 0; kb < SEQ; kb += 64) {
        __syncthreads();
        #pragma unroll
        for (int i = 0; i < 8; i++) {
            int vid = t + i * 256;
            int row = vid >> 5;
            int c4  = (vid & 31) * 4;
            float4 v = ld4(g_qkv + (size_t)(kb + row) * TD + DIM + h * HD + c4);
            float* d = ks + row * QK_STRIDE + c4;
            d[0] = v.x; d[1] = v.y; d[2] = v.z; d[3] = v.w;
        }
        if (t < 64) sk[t] = seg[kb + t];
        __syncthreads();

        u64t s2[4][4];
        #pragma unroll
        for (int i = 0; i < 4; i++)
            #pragma unroll
            for (int j = 0; j < 4; j++) s2[i][j] = 0ull;

        #pragma unroll 8
        for (int kk = 0; kk < HD; kk += 2) {
            u64t a2[4], b2[4];
            #pragma unroll
            for (int i = 0; i < 4; i++) {
                float2 v = *(const float2*)&qs[(ty + 16 * i) * QK_STRIDE + kk];
                a2[i] = pk(v.x, v.y);
            }
            #pragma unroll
            for (int j = 0; j < 4; j++) {
                float2 v = *(const float2*)&ks[(tx + 16 * j) * QK_STRIDE + kk];
                b2[j] = pk(v.x, v.y);
            }
            #pragma unroll
            for (int i = 0; i < 4; i++)
                #pragma unroll
                for (int j = 0; j < 4; j++)
                    fma2(s2[i][j], a2[i], b2[j]);
        }

        #pragma unroll
        for (int i = 0; i < 4; i++) {
            int r = ty + 16 * i;
            int sgq = sq[r];
            float s[4];
            float rm = -1e30f;
            #pragma unroll
            for (int j = 0; j < 4; j++) {
                float2 v = upk(s2[i][j]);
                s[j] = v.x + v.y + ((sgq == sk[tx + 16 * j]) ? 1.0f : 0.0f);
                rm = fmaxf(rm, s[j]);
            }
            #pragma unroll
            for (int off = 8; off > 0; off >>= 1)
                rm = fmaxf(rm, __shfl_xor_sync(0xffffffffu, rm, off));
            float mnew = fmaxf(m_i[i], rm);
            float corr = __expf(m_i[i] - mnew);
            m_i[i] = mnew;
            float rsum = 0.f;
            #pragma unroll
            for (int j = 0; j < 4; j++) {
                s[j] = __expf(s[j] - mnew);
                rsum += s[j];
            }
            #pragma unroll
            for (int off = 8; off > 0; off >>= 1)
                rsum += __shfl_xor_sync(0xffffffffu, rsum, off);
            l_i[i] = l_i[i] * corr + rsum;
            u64t corr2 = pk(corr, corr);
            #pragma unroll
            for (int c = 0; c < 4; c++) mul2(o2[i][c], corr2);
            #pragma unroll
            for (int j = 0; j < 4; j++)
                ps[r * P_STRIDE + tx + 16 * j] = s[j];
        }
        __syncthreads();

        #pragma unroll
        for (int i = 0; i < 8; i++) {
            int vid = t + i * 256;
            int row = vid >> 5;
            int c4  = (vid & 31) * 4;
            float4 v = ld4(g_qkv + (size_t)(kb + row) * TD + 2 * DIM + h * HD + c4);
            float* d = ks + row * QK_STRIDE + c4;
            d[0] = v.x; d[1] = v.y; d[2] = v.z; d[3] = v.w;
        }
        __syncthreads();

        #pragma unroll 4
        for (int j2 = 0; j2 < 64; j2++) {
            float4 v0 = *(const float4*)&ks[j2 * QK_STRIDE + tx * 4];
            float4 v1 = *(const float4*)&ks[j2 * QK_STRIDE + 64 + tx * 4];
            u64t vp[4] = { pk(v0.x, v0.y), pk(v0.z, v0.w),
                           pk(v1.x, v1.y), pk(v1.z, v1.w) };
            u64t pd[4];
            #pragma unroll
            for (int i = 0; i < 4; i++) {
                float p = ps[(ty + 16 * i) * P_STRIDE + j2];
                pd[i] = pk(p, p);
            }
            #pragma unroll
            for (int i = 0; i < 4; i++)
                #pragma unroll
                for (int c = 0; c < 4; c++)
                    fma2(o2[i][c], pd[i], vp[c]);
        }
    }

    #pragma unroll
    for (int i = 0; i < 4; i++) {
        float inv = 1.0f / l_i[i];
        size_t rbase = (size_t)(q0 + ty + 16 * i) * DIM + h * HD;
        float2 p0 = upk(o2[i][0]), p1 = upk(o2[i][1]);
        float2 p2 = upk(o2[i][2]), p3 = upk(o2[i][3]);
        __half2 w0[2] = { __floats2half2_rn(p0.x * inv, p0.y * inv),
                          __floats2half2_rn(p1.x * inv, p1.y * inv) };
        __half2 w1[2] = { __floats2half2_rn(p2.x * inv, p2.y * inv),
                          __floats2half2_rn(p3.x * inv, p3.y * inv) };
        *(uint2*)(g_attn_h + rbase + tx * 4) = *(uint2*)w0;
        *(uint2*)(g_attn_h + rbase + 64 + tx * 4) = *(uint2*)w1;
    }
}

// ======================= launcher =======================
extern "C" void kernel_launch(void* const* d_in, const int* in_sizes, int n_in,
                              void* d_out, int out_size)
{
    const float* byte_repr = (const float*)d_in[0];
    const int*   categories= (const int*)  d_in[1];
    const int*   cse       = (const int*)  d_in[2];
    const int*   comb      = (const int*)  d_in[3];
    const int*   seg_ids   = (const int*)  d_in[4];
    const float* cat_emb   = (const float*)d_in[5];
    const float* case_emb  = (const float*)d_in[6];
    const float* comb_emb  = (const float*)d_in[7];
    const float* ln_g      = (const float*)d_in[8];
    const float* ln_b      = (const float*)d_in[9];
    const float* in_w      = (const float*)d_in[10];
    const float* in_b      = (const float*)d_in[11];
    const float* out_w     = (const float*)d_in[12];
    const float* out_b     = (const float*)d_in[13];
    float* out = (float*)d_out;

    float *p_xn, *p_qkv;
    __half *p_xn_h, *p_attn_h, *p_w1_h, *p_w2_h;
    cudaGetSymbolAddress((void**)&p_xn,    g_xn);
    cudaGetSymbolAddress((void**)&p_qkv,   g_qkv);
    cudaGetSymbolAddress((void**)&p_xn_h,  g_xn_h);
    cudaGetSymbolAddress((void**)&p_attn_h,g_attn_h);
    cudaGetSymbolAddress((void**)&p_w1_h,  g_w1_h);
    cudaGetSymbolAddress((void**)&p_w2_h,  g_w2_h);

    cudaFuncSetAttribute(k_attn, cudaFuncAttributeMaxDynamicSharedMemorySize, ATTN_SMEM);

    // weight converts (independent of LN)
    k_conv_h<<<(TD * DIM / 8 + 255) / 256, 256>>>(in_w, p_w1_h, TD * DIM / 8);
    k_conv_h<<<(DIM * DIM / 8 + 255) / 256, 256>>>(out_w, p_w2_h, DIM * DIM / 8);

    // 1) fused embed + LN (+f16 copy)
    k_embed_ln<<<SEQ, 256>>>(byte_repr, categories, cse, comb,
                             cat_emb, case_emb, comb_emb, ln_g, ln_b);

    // 2) QKV projection: [S,3D] = xn @ in_w^T + in_b   (HMMA f16)
    dim3 gq(TD / 128, SEQ / 128);
    h_gemm<<<gq, 256>>>(p_xn_h, p_w1_h, in_b, nullptr, p_qkv, SEQ, TD, DIM);

    // 3) attention (f32x2, writes f16)
    dim3 ga(SEQ / 64, NH);
    k_attn<<<ga, 256, ATTN_SMEM>>>(seg_ids);

    // 4) out projection + residual: out = xn + attn @ out_w^T + out_b  (HMMA f16)
    dim3 go(DIM / 128, SEQ / 128);
    h_gemm<<<go, 256>>>(p_attn_h, p_w2_h, out_b, p_xn, out, SEQ, DIM, DIM);
}

// round 5
// speedup vs baseline: 7.3346x; 2.8006x over previous
#include <cuda_runtime.h>
#include <cuda_fp16.h>
#include <cstdint>

#define SEQ 2048
#define DIM 2048
#define NH  16
#define HD  128
#define TD  (3*DIM)
#define LN_EPS 1e-5f

// ---------------- scratch (static device globals; no allocation) ----------------
__device__ float  g_xn[(size_t)SEQ*DIM];      // LayerNorm output fp32 (residual)
__device__ __half g_xn_h[(size_t)SEQ*DIM];    // f16 LN output (GEMM A operand)
__device__ __half g_qkv_h[(size_t)SEQ*TD];    // f16 QKV
__device__ __half g_attn_h[(size_t)SEQ*DIM];  // f16 attention output
__device__ __half g_w1_h[(size_t)TD*DIM];
__device__ __half g_w2_h[(size_t)DIM*DIM];

__device__ __forceinline__ float4 ld4(const float* p){ return *(const float4*)p; }

// ---------------- MMA helpers ----------------
__device__ __forceinline__ uint32_t smem_u32(const void* p){
    uint32_t a; asm("{ .reg .u64 t; cvta.to.shared.u64 t, %1; cvt.u32.u64 %0, t; }" : "=r"(a) : "l"(p)); return a;
}
__device__ __forceinline__ void ldsm4(uint32_t& r0, uint32_t& r1, uint32_t& r2, uint32_t& r3, uint32_t a){
    asm volatile("ldmatrix.sync.aligned.m8n8.x4.shared.b16 {%0,%1,%2,%3}, [%4];"
                 : "=r"(r0), "=r"(r1), "=r"(r2), "=r"(r3) : "r"(a));
}
__device__ __forceinline__ void ldsm4t(uint32_t& r0, uint32_t& r1, uint32_t& r2, uint32_t& r3, uint32_t a){
    asm volatile("ldmatrix.sync.aligned.m8n8.x4.trans.shared.b16 {%0,%1,%2,%3}, [%4];"
                 : "=r"(r0), "=r"(r1), "=r"(r2), "=r"(r3) : "r"(a));
}
__device__ __forceinline__ void mma16816(float* c, uint32_t a0, uint32_t a1, uint32_t a2, uint32_t a3,
                                         uint32_t b0, uint32_t b1){
    asm volatile("mma.sync.aligned.m16n8k16.row.col.f32.f16.f16.f32 "
                 "{%0,%1,%2,%3}, {%4,%5,%6,%7}, {%8,%9}, {%0,%1,%2,%3};"
                 : "+f"(c[0]), "+f"(c[1]), "+f"(c[2]), "+f"(c[3])
                 : "r"(a0), "r"(a1), "r"(a2), "r"(a3), "r"(b0), "r"(b1));
}
__device__ __forceinline__ void cpasync16(uint32_t dst, const void* src){
    asm volatile("cp.async.cg.shared.global [%0], [%1], 16;" :: "r"(dst), "l"(src));
}
__device__ __forceinline__ uint32_t h2u(__half2 h){ return *(uint32_t*)&h; }

// ================= HMMA f16 GEMM-NT =================
// C[m,n] = sum_k A[m,k]*B[n,k] + bias[n] (+resid). Writes fp32 (Cf) or f16 (Ch).
#define BK 32
#define TSTR 40

__global__ void __launch_bounds__(256) h_gemm(
    const __half* __restrict__ A, const __half* __restrict__ B,
    const float* __restrict__ bias, const float* __restrict__ resid,
    float* __restrict__ Cf, __half* __restrict__ Ch, int M, int N, int K)
{
    __shared__ __half As[2][128 * TSTR];
    __shared__ __half Bs[2][128 * TSTR];

    int t = threadIdx.x, lane = t & 31, w = t >> 5;
    int bm = blockIdx.y * 128, bn = blockIdx.x * 128;
    int wm = (w >> 2) * 64, wn = (w & 3) * 32;

    uint32_t as_base[2] = { smem_u32(As[0]), smem_u32(As[1]) };
    uint32_t bs_base[2] = { smem_u32(Bs[0]), smem_u32(Bs[1]) };

    int a_row = wm + (lane & 7) + ((lane & 8) ? 8 : 0);
    int a_kof = (lane & 16) ? 8 : 0;
    int b_row = wn + (lane & 7) + ((lane & 16) ? 8 : 0);
    int b_kof = (lane & 8) ? 8 : 0;

    float acc[4][4][4];
    #pragma unroll
    for (int i = 0; i < 4; i++)
        #pragma unroll
        for (int j = 0; j < 4; j++)
            #pragma unroll
            for (int c = 0; c < 4; c++) acc[i][j][c] = 0.f;

    int niter = K / BK;

    {
        #pragma unroll
        for (int i = 0; i < 2; i++) {
            int vid = t + i * 256;
            int row = vid >> 2, c = vid & 3;
            cpasync16(as_base[0] + (row * TSTR + c * 8) * 2, A + (size_t)(bm + row) * K + c * 8);
            cpasync16(bs_base[0] + (row * TSTR + c * 8) * 2, B + (size_t)(bn + row) * K + c * 8);
        }
        asm volatile("cp.async.commit_group;" ::: "memory");
    }

    for (int kt = 0; kt < niter; kt++) {
        int buf = kt & 1;
        if (kt + 1 < niter) {
            int nb = buf ^ 1;
            const __half* Ak = A + (size_t)(kt + 1) * BK;
            const __half* Bk = B + (size_t)(kt + 1) * BK;
            #pragma unroll
            for (int i = 0; i < 2; i++) {
                int vid = t + i * 256;
                int row = vid >> 2, c = vid & 3;
                cpasync16(as_base[nb] + (row * TSTR + c * 8) * 2, Ak + (size_t)(bm + row) * K + c * 8);
                cpasync16(bs_base[nb] + (row * TSTR + c * 8) * 2, Bk + (size_t)(bn + row) * K + c * 8);
            }
            asm volatile("cp.async.commit_group;" ::: "memory");
            asm volatile("cp.async.wait_group 1;" ::: "memory");
        } else {
            asm volatile("cp.async.wait_group 0;" ::: "memory");
        }
        __syncthreads();

        uint32_t abase = as_base[buf], bbase = bs_base[buf];
        #pragma unroll
        for (int ks = 0; ks < 2; ks++) {
            uint32_t a[4][4], b[2][4];
            #pragma unroll
            for (int i = 0; i < 4; i++) {
                uint32_t addr = abase + (((a_row + i * 16) * TSTR) + ks * 16 + a_kof) * 2;
                ldsm4(a[i][0], a[i][1], a[i][2], a[i][3], addr);
            }
            #pragma unroll
            for (int p = 0; p < 2; p++) {
                uint32_t addr = bbase + (((b_row + p * 16) * TSTR) + ks * 16 + b_kof) * 2;
                ldsm4(b[p][0], b[p][1], b[p][2], b[p][3], addr);
            }
            #pragma unroll
            for (int i = 0; i < 4; i++) {
                #pragma unroll
                for (int j = 0; j < 4; j++) {
                    int p = j >> 1;
                    uint32_t bb0 = (j & 1) ? b[p][2] : b[p][0];
                    uint32_t bb1 = (j & 1) ? b[p][3] : b[p][1];
                    mma16816(acc[i][j], a[i][0], a[i][1], a[i][2], a[i][3], bb0, bb1);
                }
            }
        }
        __syncthreads();
    }

    int mrow = bm + wm + (lane >> 2);
    int ncol = bn + wn + 2 * (lane & 3);
    #pragma unroll
    for (int i = 0; i < 4; i++) {
        #pragma unroll
        for (int j = 0; j < 4; j++) {
            int n0 = ncol + j * 8;
            float b0 = bias[n0], b1 = bias[n0 + 1];
            int m0 = mrow + i * 16;
            size_t rb0 = (size_t)m0 * N + n0;
            size_t rb1 = (size_t)(m0 + 8) * N + n0;
            float2 v0 = { acc[i][j][0] + b0, acc[i][j][1] + b1 };
            float2 v1 = { acc[i][j][2] + b0, acc[i][j][3] + b1 };
            if (Ch) {
                *(uint32_t*)(Ch + rb0) = h2u(__floats2half2_rn(v0.x, v0.y));
                *(uint32_t*)(Ch + rb1) = h2u(__floats2half2_rn(v1.x, v1.y));
            } else {
                if (resid) {
                    float2 r0 = *(const float2*)(resid + rb0);
                    float2 r1 = *(const float2*)(resid + rb1);
                    v0.x += r0.x; v0.y += r0.y; v1.x += r1.x; v1.y += r1.y;
                }
                *(float2*)(Cf + rb0) = v0;
                *(float2*)(Cf + rb1) = v1;
            }
        }
    }
}

// ======================= HMMA flash attention =======================
// grid (SEQ/128, NH), 256 threads (8 warps x 16 q-rows). BK=64 kv per tile.
#define TSTR2 136                       // f16 row stride for 128-wide tiles
#define TILE_E (64 * TSTR2)             // elements per K or V tile
#define STAGE_E (2 * TILE_E)            // K+V per stage
#define ATTN_SMEM (2 * STAGE_E * 2 + 512)

__global__ void __launch_bounds__(256, 1) k_attn_h(
    const int* __restrict__ seg,
    const __half* __restrict__ qkv,
    __half* __restrict__ attn_out)
{
    extern __shared__ char smc[];
    __half* buf = (__half*)smc;
    uint32_t buf_u = smem_u32(buf);
    uint32_t sks_u = buf_u + 2 * STAGE_E * 2;
    int* sks = (int*)(smc + 2 * STAGE_E * 2);

    const int t = threadIdx.x, lane = t & 31, w = t >> 5;
    const int q0 = blockIdx.x * 128, h = blockIdx.y;
    const int wq = w * 16;
    const float scale = 0.08838834764831845f;

    const int ldrow = (lane & 7) + ((lane & 8) ? 8 : 0);   // A/trans row offset
    const int a_kof = (lane & 16) ? 8 : 0;
    const int b_row = (lane & 7) + ((lane & 16) ? 8 : 0);  // B (non-trans) row offset
    const int b_kof = (lane & 8) ? 8 : 0;
    const int v_col = (lane & 16) ? 8 : 0;                  // trans col offset

    // ---- load Q tile [128 x 128] into smem (overlay stage area), then to regs ----
    #pragma unroll
    for (int i = 0; i < 8; i++) {
        int vid = t + i * 256;
        int row = vid >> 4, c = vid & 15;
        cpasync16(buf_u + (row * TSTR2 + c * 8) * 2,
                  qkv + (size_t)(q0 + row) * TD + h * HD + c * 8);
    }
    asm volatile("cp.async.commit_group;" ::: "memory");
    asm volatile("cp.async.wait_group 0;" ::: "memory");
    __syncthreads();

    uint32_t qa[8][4];
    #pragma unroll
    for (int ks = 0; ks < 8; ks++) {
        uint32_t addr = buf_u + (((wq + ldrow) * TSTR2) + ks * 16 + a_kof) * 2;
        ldsm4(qa[ks][0], qa[ks][1], qa[ks][2], qa[ks][3], addr);
    }
    int sq0 = seg[q0 + wq + (lane >> 2)];
    int sq1 = seg[q0 + wq + (lane >> 2) + 8];
    __syncthreads();

    float mv[2] = { -1e30f, -1e30f }, lv[2] = { 0.f, 0.f };
    float o[16][4];
    #pragma unroll
    for (int j = 0; j < 16; j++)
        #pragma unroll
        for (int c = 0; c < 4; c++) o[j][c] = 0.f;

    // ---- prologue: stage 0 ----
    {
        #pragma unroll
        for (int i = 0; i < 4; i++) {
            int vid = t + i * 256;
            int row = vid >> 4, c = vid & 15;
            cpasync16(buf_u + (row * TSTR2 + c * 8) * 2,
                      qkv + (size_t)row * TD + DIM + h * HD + c * 8);
            cpasync16(buf_u + (TILE_E + row * TSTR2 + c * 8) * 2,
                      qkv + (size_t)row * TD + 2 * DIM + h * HD + c * 8);
        }
        if (t < 16) cpasync16(sks_u + t * 16, seg + t * 4);
        asm volatile("cp.async.commit_group;" ::: "memory");
    }

    const int NT = SEQ / 64;
    for (int kt = 0; kt < NT; kt++) {
        int st = kt & 1;
        if (kt + 1 < NT) {
            int ns = st ^ 1;
            int kb = (kt + 1) * 64;
            #pragma unroll
            for (int i = 0; i < 4; i++) {
                int vid = t + i * 256;
                int row = vid >> 4, c = vid & 15;
                cpasync16(buf_u + (ns * STAGE_E + row * TSTR2 + c * 8) * 2,
                          qkv + (size_t)(kb + row) * TD + DIM + h * HD + c * 8);
                cpasync16(buf_u + (ns * STAGE_E + TILE_E + row * TSTR2 + c * 8) * 2,
                          qkv + (size_t)(kb + row) * TD + 2 * DIM + h * HD + c * 8);
            }
            if (t < 16) cpasync16(sks_u + ns * 256 + t * 16, seg + kb + t * 4);
            asm volatile("cp.async.commit_group;" ::: "memory");
            asm volatile("cp.async.wait_group 1;" ::: "memory");
        } else {
            asm volatile("cp.async.wait_group 0;" ::: "memory");
        }
        __syncthreads();

        uint32_t kbase = buf_u + (st * STAGE_E) * 2;
        uint32_t vbase = kbase + TILE_E * 2;
        const int* skp = sks + st * 64;

        // ---- S = Q @ K^T  (16 x 64 per warp) ----
        float s[8][4];
        #pragma unroll
        for (int j = 0; j < 8; j++)
            #pragma unroll
            for (int c = 0; c < 4; c++) s[j][c] = 0.f;

        #pragma unroll
        for (int ks = 0; ks < 8; ks++) {
            uint32_t kb_[4][4];
            #pragma unroll
            for (int g = 0; g < 4; g++) {
                uint32_t addr = kbase + (((g * 16 + b_row) * TSTR2) + ks * 16 + b_kof) * 2;
                ldsm4(kb_[g][0], kb_[g][1], kb_[g][2], kb_[g][3], addr);
            }
            #pragma unroll
            for (int g = 0; g < 4; g++) {
                mma16816(s[2*g],   qa[ks][0], qa[ks][1], qa[ks][2], qa[ks][3], kb_[g][0], kb_[g][1]);
                mma16816(s[2*g+1], qa[ks][0], qa[ks][1], qa[ks][2], qa[ks][3], kb_[g][2], kb_[g][3]);
            }
        }

        // ---- softmax (online) in acc layout ----
        #pragma unroll
        for (int rh = 0; rh < 2; rh++) {
            int sqv = rh ? sq1 : sq0;
            float rm = -1e30f;
            #pragma unroll
            for (int j = 0; j < 8; j++) {
                #pragma unroll
                for (int cc = 0; cc < 2; cc++) {
                    int col = 8 * j + 2 * (lane & 3) + cc;
                    float v = s[j][2*rh+cc] * scale + ((sqv == skp[col]) ? 1.0f : 0.0f);
                    s[j][2*rh+cc] = v;
                    rm = fmaxf(rm, v);
                }
            }
            rm = fmaxf(rm, __shfl_xor_sync(0xffffffffu, rm, 1));
            rm = fmaxf(rm, __shfl_xor_sync(0xffffffffu, rm, 2));
            float mnew = fmaxf(mv[rh], rm);
            float corr = __expf(mv[rh] - mnew);
            mv[rh] = mnew;
            float rs = 0.f;
            #pragma unroll
            for (int j = 0; j < 8; j++) {
                #pragma unroll
                for (int cc = 0; cc < 2; cc++) {
                    float e = __expf(s[j][2*rh+cc] - mnew);
                    s[j][2*rh+cc] = e;
                    rs += e;
                }
            }
            rs += __shfl_xor_sync(0xffffffffu, rs, 1);
            rs += __shfl_xor_sync(0xffffffffu, rs, 2);
            lv[rh] = lv[rh] * corr + rs;
            #pragma unroll
            for (int j = 0; j < 16; j++) {
                o[j][2*rh]   *= corr;
                o[j][2*rh+1] *= corr;
            }
        }

        // ---- pack P to A-fragments ----
        uint32_t pa[4][4];
        #pragma unroll
        for (int kk = 0; kk < 4; kk++) {
            pa[kk][0] = h2u(__floats2half2_rn(s[2*kk][0],   s[2*kk][1]));
            pa[kk][1] = h2u(__floats2half2_rn(s[2*kk][2],   s[2*kk][3]));
            pa[kk][2] = h2u(__floats2half2_rn(s[2*kk+1][0], s[2*kk+1][1]));
            pa[kk][3] = h2u(__floats2half2_rn(s[2*kk+1][2], s[2*kk+1][3]));
        }

        // ---- O += P @ V  (V via ldmatrix.trans) ----
        #pragma unroll
        for (int kk = 0; kk < 4; kk++) {
            #pragma unroll
            for (int g = 0; g < 8; g++) {
                uint32_t vb0, vb1, vb2, vb3;
                uint32_t addr = vbase + (((kk * 16 + ldrow) * TSTR2) + g * 16 + v_col) * 2;
                ldsm4t(vb0, vb1, vb2, vb3, addr);
                mma16816(o[2*g],   pa[kk][0], pa[kk][1], pa[kk][2], pa[kk][3], vb0, vb1);
                mma16816(o[2*g+1], pa[kk][0], pa[kk][1], pa[kk][2], pa[kk][3], vb2, vb3);
            }
        }
        __syncthreads();
    }

    // ---- normalize, write f16 ----
    float inv0 = 1.0f / lv[0], inv1 = 1.0f / lv[1];
    int r0 = q0 + wq + (lane >> 2);
    int colb = 2 * (lane & 3);
    #pragma unroll
    for (int j = 0; j < 16; j++) {
        int col = h * HD + 8 * j + colb;
        *(uint32_t*)(attn_out + (size_t)r0 * DIM + col) =
            h2u(__floats2half2_rn(o[j][0] * inv0, o[j][1] * inv0));
        *(uint32_t*)(attn_out + (size_t)(r0 + 8) * DIM + col) =
            h2u(__floats2half2_rn(o[j][2] * inv1, o[j][3] * inv1));
    }
}

// ======================= fp32 -> f16 convert =======================
__global__ void __launch_bounds__(256) k_conv_h(const float* __restrict__ src,
                                               __half* __restrict__ dst, int n8)
{
    int i = blockIdx.x * 256 + threadIdx.x;
    if (i >= n8) return;
    float4 a = ld4(src + (size_t)i * 8);
    float4 b = ld4(src + (size_t)i * 8 + 4);
    __half2 h[4];
    h[0] = __floats2half2_rn(a.x, a.y);
    h[1] = __floats2half2_rn(a.z, a.w);
    h[2] = __floats2half2_rn(b.x, b.y);
    h[3] = __floats2half2_rn(b.z, b.w);
    *(uint4*)(dst + (size_t)i * 8) = *(uint4*)h;
}

// ======================= kernel 1: fused embed + LayerNorm (+f16 copy) =======================
__global__ void __launch_bounds__(256) k_embed_ln(
    const float* __restrict__ byte_repr,
    const int*   __restrict__ cats,
    const int*   __restrict__ cse,
    const int*   __restrict__ comb,
    const float* __restrict__ cat_emb,
    const float* __restrict__ case_emb,
    const float* __restrict__ comb_emb,
    const float* __restrict__ g,
    const float* __restrict__ b)
{
    int s = blockIdx.x;
    int t = threadIdx.x;
    int lane = t & 31, wid = t >> 5;
    int c0 = t * 4;
    int c1 = 1024 + t * 4;

    size_t catb = (size_t)cats[s] * DIM;
    size_t cab  = (size_t)cse[s]  * DIM;
    size_t cob  = (size_t)comb[s] * DIM;
    const float* base = byte_repr + (size_t)s * DIM;

    float x[8];
    {
        float4 a = ld4(base + c0), e = ld4(cat_emb + catb + c0);
        float4 f = ld4(case_emb + cab + c0), h = ld4(comb_emb + cob + c0);
        x[0] = a.x + e.x + f.x + h.x;  x[1] = a.y + e.y + f.y + h.y;
        x[2] = a.z + e.z + f.z + h.z;  x[3] = a.w + e.w + f.w + h.w;
    }
    {
        float4 a = ld4(base + c1), e = ld4(cat_emb + catb + c1);
        float4 f = ld4(case_emb + cab + c1), h = ld4(comb_emb + cob + c1);
        x[4] = a.x + e.x + f.x + h.x;  x[5] = a.y + e.y + f.y + h.y;
        x[6] = a.z + e.z + f.z + h.z;  x[7] = a.w + e.w + f.w + h.w;
    }

    __shared__ float red[8];
    __shared__ float s_bcast;

    float sum = 0.f;
    #pragma unroll
    for (int i = 0; i < 8; i++) sum += x[i];
    #pragma unroll
    for (int o = 16; o > 0; o >>= 1) sum += __shfl_xor_sync(0xffffffffu, sum, o);
    if (lane == 0) red[wid] = sum;
    __syncthreads();
    if (t == 0) {
        float v = 0.f;
        #pragma unroll
        for (int i = 0; i < 8; i++) v += red[i];
        s_bcast = v * (1.0f / DIM);
    }
    __syncthreads();
    float mu = s_bcast;
    __syncthreads();

    float sq = 0.f;
    #pragma unroll
    for (int i = 0; i < 8; i++) { float d = x[i] - mu; sq += d * d; }
    #pragma unroll
    for (int o = 16; o > 0; o >>= 1) sq += __shfl_xor_sync(0xffffffffu, sq, o);
    if (lane == 0) red[wid] = sq;
    __syncthreads();
    if (t == 0) {
        float v = 0.f;
        #pragma unroll
        for (int i = 0; i < 8; i++) v += red[i];
        s_bcast = rsqrtf(v * (1.0f / DIM) + LN_EPS);
    }
    __syncthreads();
    float rs = s_bcast;

    float* dst = g_xn + (size_t)s * DIM;
    __half* dsth = g_xn_h + (size_t)s * DIM;
    {
        float4 gg = ld4(g + c0), bb = ld4(b + c0);
        float4 o;
        o.x = (x[0] - mu) * rs * gg.x + bb.x;
        o.y = (x[1] - mu) * rs * gg.y + bb.y;
        o.z = (x[2] - mu) * rs * gg.z + bb.z;
        o.w = (x[3] - mu) * rs * gg.w + bb.w;
        *(float4*)(dst + c0) = o;
        __half2 h2[2] = { __floats2half2_rn(o.x, o.y), __floats2half2_rn(o.z, o.w) };
        *(uint2*)(dsth + c0) = *(uint2*)h2;
    }
    {
        float4 gg = ld4(g + c1), bb = ld4(b + c1);
        float4 o;
        o.x = (x[4] - mu) * rs * gg.x + bb.x;
        o.y = (x[5] - mu) * rs * gg.y + bb.y;
        o.z = (x[6] - mu) * rs * gg.z + bb.z;
        o.w = (x[7] - mu) * rs * gg.w + bb.w;
        *(float4*)(dst + c1) = o;
        __half2 h2[2] = { __floats2half2_rn(o.x, o.y), __floats2half2_rn(o.z, o.w) };
        *(uint2*)(dsth + c1) = *(uint2*)h2;
    }
}

// ======================= launcher =======================
extern "C" void kernel_launch(void* const* d_in, const int* in_sizes, int n_in,
                              void* d_out, int out_size)
{
    const float* byte_repr = (const float*)d_in[0];
    const int*   categories= (const int*)  d_in[1];
    const int*   cse       = (const int*)  d_in[2];
    const int*   comb      = (const int*)  d_in[3];
    const int*   seg_ids   = (const int*)  d_in[4];
    const float* cat_emb   = (const float*)d_in[5];
    const float* case_emb  = (const float*)d_in[6];
    const float* comb_emb  = (const float*)d_in[7];
    const float* ln_g      = (const float*)d_in[8];
    const float* ln_b      = (const float*)d_in[9];
    const float* in_w      = (const float*)d_in[10];
    const float* in_b      = (const float*)d_in[11];
    const float* out_w     = (const float*)d_in[12];
    const float* out_b     = (const float*)d_in[13];
    float* out = (float*)d_out;

    float *p_xn;
    __half *p_xn_h, *p_qkv_h, *p_attn_h, *p_w1_h, *p_w2_h;
    cudaGetSymbolAddress((void**)&p_xn,    g_xn);
    cudaGetSymbolAddress((void**)&p_xn_h,  g_xn_h);
    cudaGetSymbolAddress((void**)&p_qkv_h, g_qkv_h);
    cudaGetSymbolAddress((void**)&p_attn_h,g_attn_h);
    cudaGetSymbolAddress((void**)&p_w1_h,  g_w1_h);
    cudaGetSymbolAddress((void**)&p_w2_h,  g_w2_h);

    cudaFuncSetAttribute(k_attn_h, cudaFuncAttributeMaxDynamicSharedMemorySize, ATTN_SMEM);

    // weight converts
    k_conv_h<<<(TD * DIM / 8 + 255) / 256, 256>>>(in_w, p_w1_h, TD * DIM / 8);
    k_conv_h<<<(DIM * DIM / 8 + 255) / 256, 256>>>(out_w, p_w2_h, DIM * DIM / 8);

    // 1) fused embed + LN (+f16 copy)
    k_embed_ln<<<SEQ, 256>>>(byte_repr, categories, cse, comb,
                             cat_emb, case_emb, comb_emb, ln_g, ln_b);

    // 2) QKV projection -> f16
    dim3 gq(TD / 128, SEQ / 128);
    h_gemm<<<gq, 256>>>(p_xn_h, p_w1_h, in_b, nullptr, nullptr, p_qkv_h, SEQ, TD, DIM);

    // 3) HMMA flash attention
    dim3 ga(SEQ / 128, NH);
    k_attn_h<<<ga, 256, ATTN_SMEM>>>(seg_ids, p_qkv_h, p_attn_h);

    // 4) out projection + residual -> fp32 out
    dim3 go(DIM / 128, SEQ / 128);
    h_gemm<<<go, 256>>>(p_attn_h, p_w2_h, out_b, p_xn, out, nullptr, SEQ, DIM, DIM);
}